// round 11
// baseline (speedup 1.0000x reference)
#include <cuda_runtime.h>
#include <cuda_fp16.h>
#include <cstdint>

#define MDIM 16384
#define NDIM 4096
#define KDIM 4096
#define BM 128
#define BN 256
#define BK 32
#define NKT (KDIM / BK)             // 128
// stage: A fp32 128 rows x 144B (pad) = 18432; B fp16 256 rows x 64B = 16384
#define A_STAGE 18432
#define STAGE_BYTES (A_STAGE + 16384)     // 34816
#define SMEM_BYTES (3 * STAGE_BYTES)      // 104448
#define NTHR 512

// fp16 W operand, word-transposed within each 64-byte (32-col) block:
//   new_word[(o&3)*4 + (o>>2)] = old_word[o]
// so mma-thread t's four needed words are one LDS.128 per row per block.
__device__ __half g_wh[(size_t)NDIM * KDIM];

// ---------------- helpers ----------------
__device__ __forceinline__ uint32_t smem_u32(const void* p) {
    uint32_t a;
    asm("{ .reg .u64 t; cvta.to.shared.u64 t, %1; cvt.u32.u64 %0, t; }" : "=r"(a) : "l"(p));
    return a;
}
__device__ __forceinline__ void cp_async16(uint32_t saddr, const void* gptr) {
    asm volatile("cp.async.cg.shared.global [%0], [%1], 16;"
                 :: "r"(saddr), "l"(__cvta_generic_to_global(gptr)) : "memory");
}
#define CP_COMMIT() asm volatile("cp.async.commit_group;" ::: "memory")
#define CP_WAIT1()  asm volatile("cp.async.wait_group 1;" ::: "memory")
#define CP_WAIT0()  asm volatile("cp.async.wait_group 0;" ::: "memory")

__device__ __forceinline__ uint4 lds128(uint32_t addr) {
    uint4 v;
    asm volatile("ld.shared.v4.b32 {%0,%1,%2,%3}, [%4];"
                 : "=r"(v.x), "=r"(v.y), "=r"(v.z), "=r"(v.w) : "r"(addr));
    return v;
}
__device__ __forceinline__ void hmma(float c[4], uint32_t a0, uint32_t a1,
                                     uint32_t a2, uint32_t a3,
                                     uint32_t b0, uint32_t b1) {
    asm volatile(
        "mma.sync.aligned.m16n8k16.row.col.f32.f16.f16.f32 "
        "{%0,%1,%2,%3}, {%4,%5,%6,%7}, {%8,%9}, {%0,%1,%2,%3};"
        : "+f"(c[0]), "+f"(c[1]), "+f"(c[2]), "+f"(c[3])
        : "r"(a0), "r"(a1), "r"(a2), "r"(a3), "r"(b0), "r"(b1));
}
// two fp32 -> packed half2 word
__device__ __forceinline__ uint32_t f2h2(float2 f) {
    uint32_t r;
    asm("cvt.rn.f16x2.f32 %0, %2, %1;" : "=r"(r) : "f"(f.x), "f"(f.y));
    return r;
}
// transposed word position within a 64B block
__device__ __forceinline__ int tpos(int o) { return ((o & 3) << 2) | (o >> 2); }

// convert 4 consecutive fp32 cols (col0 % 4 == 0) and store word-transposed
__device__ __forceinline__ void cvt_store4(__half* dst, size_t row, int col0, float4 v) {
    __half2 h0 = __floats2half2_rn(v.x, v.y);
    __half2 h1 = __floats2half2_rn(v.z, v.w);
    char* bb = (char*)dst + row * (KDIM * 2) + (col0 >> 5) * 64;
    int W = (col0 >> 1) & 15;
    *(uint32_t*)(bb + tpos(W) * 4)     = *(uint32_t*)&h0;
    *(uint32_t*)(bb + tpos(W + 1) * 4) = *(uint32_t*)&h1;
}

// ---------------- prep: LoRA fold + fp16 permute for W only ----------------
__global__ void prep_w_kernel(const float* __restrict__ w, const float* __restrict__ lA,
                              const float* __restrict__ lB) {
    int o = blockIdx.x, tid = threadIdx.x;
    float bv[16];
#pragma unroll
    for (int r = 0; r < 16; r++) bv[r] = lB[o * 16 + r] * 2.0f;
    const float4* wr = (const float4*)(w + (size_t)o * KDIM);
#pragma unroll 4
    for (int i = 0; i < 4; i++) {
        int j = tid + 256 * i;
        float4 acc = wr[j];
#pragma unroll
        for (int r = 0; r < 16; r++) {
            float4 a = ((const float4*)(lA + (size_t)r * KDIM))[j];
            acc.x += bv[r] * a.x; acc.y += bv[r] * a.y;
            acc.z += bv[r] * a.z; acc.w += bv[r] * a.w;
        }
        cvt_store4(g_wh, o, j * 4, acc);
    }
}

// --- main GEMM: A fp32 staged + in-loop cvt, B fp16; m16n8k16; 16 warps ---
__global__ __launch_bounds__(NTHR, 1)
void lora_gemm_kernel(const float* __restrict__ x, const float* __restrict__ bias,
                      float* __restrict__ out) {
    extern __shared__ char smem[];
    const int tid = threadIdx.x;
    const int wid = tid >> 5, lane = tid & 31;
    const int wm = wid >> 2, wn = wid & 3;            // 4 x 4 warps, tile 32x64
    const int m0 = blockIdx.y * BM, n0 = blockIdx.x * BN;
    const uint32_t sbase = smem_u32(smem);

    auto issue = [&](int s, int kt) {
        uint32_t st = sbase + s * STAGE_BYTES;
#pragma unroll
        for (int i = 0; i < 2; i++) {                  // A fp32: 1024 chunks of 16B
            int c = tid + i * 512;
            int row = c >> 3, q = c & 7;
            cp_async16(st + row * 144 + q * 16,
                       x + (size_t)(m0 + row) * KDIM + kt * 32 + q * 4);
        }
#pragma unroll
        for (int i = 0; i < 2; i++) {                  // B fp16: 1024 chunks
            int c = tid + i * 512;
            int row = c >> 2, q = c & 3;
            cp_async16(st + A_STAGE + c * 16,
                       (const char*)g_wh + (size_t)(n0 + row) * (KDIM * 2) + kt * 64 + q * 16);
        }
    };

    float acc[2][8][4];
#pragma unroll
    for (int ma = 0; ma < 2; ma++)
#pragma unroll
        for (int na = 0; na < 8; na++)
#pragma unroll
            for (int j = 0; j < 4; j++) acc[ma][na][j] = 0.0f;

    issue(0, 0); CP_COMMIT();
    issue(1, 1); CP_COMMIT();

    const int g = lane >> 2, t = lane & 3;
    for (int kt = 0; kt < NKT; ++kt) {
        int s = kt - (kt / 3) * 3;
        if (kt + 2 < NKT) { CP_WAIT1(); } else { CP_WAIT0(); }
        __syncthreads();
        if (kt + 2 < NKT) {
            int s2 = (kt + 2) - ((kt + 2) / 3) * 3;
            issue(s2, kt + 2);
            CP_COMMIT();
        }

        const char* astg = smem + s * STAGE_BYTES;
        const char* arow = astg + (wm * 32 + g) * 144 + t * 8;
        uint32_t pb = sbase + s * STAGE_BYTES + A_STAGE + (wn * 64 + g) * 64 + t * 16;

        uint4 u[2], v[2], w[8];
#pragma unroll
        for (int ma = 0; ma < 2; ma++) {
            const float2* p0 = (const float2*)(arow + ma * (16 * 144));
            const float2* p1 = (const float2*)(arow + ma * (16 * 144) + 8 * 144);
            u[ma].x = f2h2(p0[0]);  u[ma].y = f2h2(p0[4]);
            u[ma].z = f2h2(p0[8]);  u[ma].w = f2h2(p0[12]);
            v[ma].x = f2h2(p1[0]);  v[ma].y = f2h2(p1[4]);
            v[ma].z = f2h2(p1[8]);  v[ma].w = f2h2(p1[12]);
        }
#pragma unroll
        for (int na = 0; na < 8; na++)
            w[na] = lds128(pb + na * (8 * 64));

        // k-group 0 (k 0..15)
#pragma unroll
        for (int ma = 0; ma < 2; ma++)
#pragma unroll
            for (int na = 0; na < 8; na++)
                hmma(acc[ma][na], u[ma].x, v[ma].x, u[ma].y, v[ma].y,
                     w[na].x, w[na].y);
        // k-group 1 (k 16..31)
#pragma unroll
        for (int ma = 0; ma < 2; ma++)
#pragma unroll
            for (int na = 0; na < 8; na++)
                hmma(acc[ma][na], u[ma].z, v[ma].z, u[ma].w, v[ma].w,
                     w[na].z, w[na].w);
    }

    // epilogue: fused bias + coalesced float2 stores
    const int r0 = m0 + wm * 32 + g;
    const int cbase = n0 + wn * 64 + t * 2;
    float2 bv[8];
#pragma unroll
    for (int na = 0; na < 8; na++)
        bv[na] = *(const float2*)(bias + cbase + na * 8);
#pragma unroll
    for (int ma = 0; ma < 2; ma++) {
        size_t row = (size_t)(r0 + ma * 16);
#pragma unroll
        for (int na = 0; na < 8; na++) {
            float2 v0 = make_float2(acc[ma][na][0] + bv[na].x, acc[ma][na][1] + bv[na].y);
            float2 v1 = make_float2(acc[ma][na][2] + bv[na].x, acc[ma][na][3] + bv[na].y);
            *(float2*)(out + row * NDIM + cbase + na * 8) = v0;
            *(float2*)(out + (row + 8) * NDIM + cbase + na * 8) = v1;
        }
    }
}

// ---------------- launch ----------------
extern "C" void kernel_launch(void* const* d_in, const int* in_sizes, int n_in,
                              void* d_out, int out_size) {
    const float* x      = (const float*)d_in[0];
    const float* weight = (const float*)d_in[1];
    const float* bias   = (const float*)d_in[2];
    const float* lora_A = (const float*)d_in[3];
    const float* lora_B = (const float*)d_in[4];
    float* out = (float*)d_out;

    cudaFuncSetAttribute(lora_gemm_kernel, cudaFuncAttributeMaxDynamicSharedMemorySize,
                         SMEM_BYTES);

    prep_w_kernel<<<NDIM, 256>>>(weight, lora_A, lora_B);
    dim3 grid(NDIM / BN, MDIM / BM);   // n fastest: fp32 x panel stays L2-resident
    lora_gemm_kernel<<<grid, NTHR, SMEM_BYTES>>>(x, bias, out);
}

// round 12
// speedup vs baseline: 1.3986x; 1.3986x over previous
#include <cuda_runtime.h>
#include <cuda_fp16.h>
#include <cstdint>

#define MDIM 16384
#define NDIM 4096
#define KDIM 4096
#define BM 128
#define BN 128
#define BK 32
#define NKT (KDIM / BK)             // 128
#define A_BYTES (BM * 64)           // 8192
#define B_BYTES (BN * 64)           // 8192
#define STAGE_BYTES (A_BYTES + B_BYTES)   // 16384
#define SMEM_BYTES (3 * STAGE_BYTES)      // 49152
#define NTHR 1024

// fp16 operands, word-transposed within each 64-byte (32-col) block:
//   new_word[(o&3)*4 + (o>>2)] = old_word[o]
// so mma-thread t's four needed words are one LDS.128 per row per block.
__device__ __half g_xh[(size_t)MDIM * KDIM];
__device__ __half g_wh[(size_t)NDIM * KDIM];

// ---------------- helpers ----------------
__device__ __forceinline__ uint32_t smem_u32(const void* p) {
    uint32_t a;
    asm("{ .reg .u64 t; cvta.to.shared.u64 t, %1; cvt.u32.u64 %0, t; }" : "=r"(a) : "l"(p));
    return a;
}
__device__ __forceinline__ void cp_async16(uint32_t saddr, const void* gptr) {
    asm volatile("cp.async.cg.shared.global [%0], [%1], 16;"
                 :: "r"(saddr), "l"(__cvta_generic_to_global(gptr)) : "memory");
}
#define CP_COMMIT() asm volatile("cp.async.commit_group;" ::: "memory")
#define CP_WAIT1()  asm volatile("cp.async.wait_group 1;" ::: "memory")
#define CP_WAIT0()  asm volatile("cp.async.wait_group 0;" ::: "memory")

__device__ __forceinline__ uint4 lds128(uint32_t addr) {
    uint4 v;
    asm volatile("ld.shared.v4.b32 {%0,%1,%2,%3}, [%4];"
                 : "=r"(v.x), "=r"(v.y), "=r"(v.z), "=r"(v.w) : "r"(addr));
    return v;
}
__device__ __forceinline__ void hmma(float c[4], uint32_t a0, uint32_t a1,
                                     uint32_t a2, uint32_t a3,
                                     uint32_t b0, uint32_t b1) {
    asm volatile(
        "mma.sync.aligned.m16n8k16.row.col.f32.f16.f16.f32 "
        "{%0,%1,%2,%3}, {%4,%5,%6,%7}, {%8,%9}, {%0,%1,%2,%3};"
        : "+f"(c[0]), "+f"(c[1]), "+f"(c[2]), "+f"(c[3])
        : "r"(a0), "r"(a1), "r"(a2), "r"(a3), "r"(b0), "r"(b1));
}
// transposed word position within a 64B block
__device__ __forceinline__ int tpos(int o) { return ((o & 3) << 2) | (o >> 2); }

// convert 4 consecutive fp32 cols (col0 % 4 == 0) and store word-transposed
__device__ __forceinline__ void cvt_store4(__half* dst, size_t row, int col0, float4 v) {
    __half2 h0 = __floats2half2_rn(v.x, v.y);
    __half2 h1 = __floats2half2_rn(v.z, v.w);
    char* bb = (char*)dst + row * (KDIM * 2) + (col0 >> 5) * 64;
    int W = (col0 >> 1) & 15;
    *(uint32_t*)(bb + tpos(W) * 4)     = *(uint32_t*)&h0;
    *(uint32_t*)(bb + tpos(W + 1) * 4) = *(uint32_t*)&h1;
}

// ---------------- merged prep: LoRA fold + fp16 permute both operands ------
__global__ void prep_kernel(const float* __restrict__ x, const float* __restrict__ w,
                            const float* __restrict__ lA, const float* __restrict__ lB) {
    int tid = threadIdx.x;
    if (blockIdx.x < NDIM) {
        int o = blockIdx.x;
        float bv[16];
#pragma unroll
        for (int r = 0; r < 16; r++) bv[r] = lB[o * 16 + r] * 2.0f;
        const float4* wr = (const float4*)(w + (size_t)o * KDIM);
#pragma unroll 4
        for (int i = 0; i < 4; i++) {
            int j = tid + 256 * i;
            float4 acc = wr[j];
#pragma unroll
            for (int r = 0; r < 16; r++) {
                float4 a = ((const float4*)(lA + (size_t)r * KDIM))[j];
                acc.x += bv[r] * a.x; acc.y += bv[r] * a.y;
                acc.z += bv[r] * a.z; acc.w += bv[r] * a.w;
            }
            cvt_store4(g_wh, o, j * 4, acc);
        }
    } else {
        size_t n4 = (size_t)MDIM * KDIM / 4;
        size_t nblk = (size_t)gridDim.x - NDIM;
        size_t stride = nblk * blockDim.x;
        const float4* in = (const float4*)x;
        for (size_t i = (blockIdx.x - NDIM) * (size_t)blockDim.x + tid; i < n4; i += stride) {
            float4 v = in[i];
            cvt_store4(g_xh, i >> 10, ((int)i & 1023) * 4, v);
        }
    }
}

// --- main GEMM: 1024 threads (8 warps/SMSP), warp grid 8x4, tile 16x32 ---
__global__ __launch_bounds__(NTHR, 1)
void lora_gemm_kernel(const float* __restrict__ bias, float* __restrict__ out) {
    extern __shared__ char smem[];
    const int tid = threadIdx.x;
    const int wid = tid >> 5, lane = tid & 31;
    const int wm = wid >> 2, wn = wid & 3;            // 8 x 4 warps
    const int m0 = blockIdx.y * BM, n0 = blockIdx.x * BN;
    const uint32_t sbase = smem_u32(smem);

    // one 16B chunk per thread per stage: tid<512 -> A, else B
    const int arow = (tid & 511) >> 2, aq = tid & 3;
    const char* gsrc;
    if (tid < 512)
        gsrc = (const char*)g_xh + (size_t)(m0 + arow) * (KDIM * 2) + aq * 16;
    else
        gsrc = (const char*)g_wh + (size_t)(n0 + arow) * (KDIM * 2) + aq * 16;
    const uint32_t sdst = (tid < 512) ? (arow * 64 + aq * 16)
                                      : (A_BYTES + arow * 64 + aq * 16);

    auto issue = [&](int s, int kt) {
        cp_async16(sbase + s * STAGE_BYTES + sdst, gsrc + (size_t)kt * 64);
    };

    float acc[4][4];
#pragma unroll
    for (int na = 0; na < 4; na++)
#pragma unroll
        for (int j = 0; j < 4; j++) acc[na][j] = 0.0f;

    issue(0, 0); CP_COMMIT();
    issue(1, 1); CP_COMMIT();

    const int g = lane >> 2, t = lane & 3;
    const uint32_t aoff = (wm * 16 + g) * 64 + t * 16;
    const uint32_t boff = A_BYTES + (wn * 32 + g) * 64 + t * 16;

    for (int kt = 0; kt < NKT; ++kt) {
        int s = kt - (kt / 3) * 3;
        if (kt + 2 < NKT) { CP_WAIT1(); } else { CP_WAIT0(); }
        __syncthreads();
        if (kt + 2 < NKT) {
            int s2 = (kt + 2) - ((kt + 2) / 3) * 3;
            issue(s2, kt + 2);
            CP_COMMIT();
        }

        uint32_t stg = sbase + s * STAGE_BYTES;
        uint4 u, v, w[4];
        u = lds128(stg + aoff);                 // A rows g, k0..31
        v = lds128(stg + aoff + 8 * 64);        // A rows g+8
#pragma unroll
        for (int na = 0; na < 4; na++)
            w[na] = lds128(stg + boff + na * (8 * 64));

        // k-group 0 (k 0..15)
#pragma unroll
        for (int na = 0; na < 4; na++)
            hmma(acc[na], u.x, v.x, u.y, v.y, w[na].x, w[na].y);
        // k-group 1 (k 16..31)
#pragma unroll
        for (int na = 0; na < 4; na++)
            hmma(acc[na], u.z, v.z, u.w, v.w, w[na].z, w[na].w);
    }

    // epilogue: fused bias + coalesced float2 stores
    const int r0 = m0 + wm * 16 + g;
    const int cbase = n0 + wn * 32 + t * 2;
#pragma unroll
    for (int na = 0; na < 4; na++) {
        float2 bv = *(const float2*)(bias + cbase + na * 8);
        float2 v0 = make_float2(acc[na][0] + bv.x, acc[na][1] + bv.y);
        float2 v1 = make_float2(acc[na][2] + bv.x, acc[na][3] + bv.y);
        *(float2*)(out + (size_t)r0 * NDIM + cbase + na * 8) = v0;
        *(float2*)(out + (size_t)(r0 + 8) * NDIM + cbase + na * 8) = v1;
    }
}

// ---------------- launch ----------------
extern "C" void kernel_launch(void* const* d_in, const int* in_sizes, int n_in,
                              void* d_out, int out_size) {
    const float* x      = (const float*)d_in[0];
    const float* weight = (const float*)d_in[1];
    const float* bias   = (const float*)d_in[2];
    const float* lora_A = (const float*)d_in[3];
    const float* lora_B = (const float*)d_in[4];
    float* out = (float*)d_out;

    cudaFuncSetAttribute(lora_gemm_kernel, cudaFuncAttributeMaxDynamicSharedMemorySize,
                         SMEM_BYTES);

    prep_kernel<<<NDIM + 8192, 256>>>(x, weight, lora_A, lora_B);
    dim3 grid(NDIM / BN, MDIM / BM);   // n fastest: x panel stays L2-resident
    lora_gemm_kernel<<<grid, NTHR, SMEM_BYTES>>>(bias, out);
}

// round 13
// speedup vs baseline: 1.6520x; 1.1812x over previous
#include <cuda_runtime.h>
#include <cuda_fp16.h>
#include <cstdint>

#define MDIM 16384
#define NDIM 4096
#define KDIM 4096
#define BM 128
#define BN 256
#define BK 32
#define NKT (KDIM / BK)             // 128
#define A_BYTES (BM * 64)           // 8192
#define B_BYTES (BN * 64)           // 16384
#define STAGE_BYTES (A_BYTES + B_BYTES)   // 24576
#define SMEM_BYTES (3 * STAGE_BYTES)      // 73728
#define NTHR 512

// fp16 operands, word-transposed within each 64-byte (32-col) block:
//   new_word[(o&3)*4 + (o>>2)] = old_word[o]
// so mma-thread t's four needed words are one LDS.128 per row per block.
__device__ __half g_xh[(size_t)MDIM * KDIM];
__device__ __half g_wh[(size_t)NDIM * KDIM];

// ---------------- helpers ----------------
__device__ __forceinline__ uint32_t smem_u32(const void* p) {
    uint32_t a;
    asm("{ .reg .u64 t; cvta.to.shared.u64 t, %1; cvt.u32.u64 %0, t; }" : "=r"(a) : "l"(p));
    return a;
}
__device__ __forceinline__ void cp_async16(uint32_t saddr, const void* gptr) {
    asm volatile("cp.async.cg.shared.global [%0], [%1], 16;"
                 :: "r"(saddr), "l"(__cvta_generic_to_global(gptr)) : "memory");
}
#define CP_COMMIT() asm volatile("cp.async.commit_group;" ::: "memory")
#define CP_WAIT1()  asm volatile("cp.async.wait_group 1;" ::: "memory")
#define CP_WAIT0()  asm volatile("cp.async.wait_group 0;" ::: "memory")

__device__ __forceinline__ uint4 lds128(uint32_t addr) {
    uint4 v;
    asm volatile("ld.shared.v4.b32 {%0,%1,%2,%3}, [%4];"
                 : "=r"(v.x), "=r"(v.y), "=r"(v.z), "=r"(v.w) : "r"(addr));
    return v;
}
__device__ __forceinline__ void hmma(float c[4], uint32_t a0, uint32_t a1,
                                     uint32_t a2, uint32_t a3,
                                     uint32_t b0, uint32_t b1) {
    asm volatile(
        "mma.sync.aligned.m16n8k16.row.col.f32.f16.f16.f32 "
        "{%0,%1,%2,%3}, {%4,%5,%6,%7}, {%8,%9}, {%0,%1,%2,%3};"
        : "+f"(c[0]), "+f"(c[1]), "+f"(c[2]), "+f"(c[3])
        : "r"(a0), "r"(a1), "r"(a2), "r"(a3), "r"(b0), "r"(b1));
}
// transposed word position within a 64B block
__device__ __forceinline__ int tpos(int o) { return ((o & 3) << 2) | (o >> 2); }

// convert 4 consecutive fp32 cols (col0 % 4 == 0) and store word-transposed
__device__ __forceinline__ void cvt_store4(__half* dst, size_t row, int col0, float4 v) {
    __half2 h0 = __floats2half2_rn(v.x, v.y);
    __half2 h1 = __floats2half2_rn(v.z, v.w);
    char* bb = (char*)dst + row * (KDIM * 2) + (col0 >> 5) * 64;
    int W = (col0 >> 1) & 15;
    *(uint32_t*)(bb + tpos(W) * 4)     = *(uint32_t*)&h0;
    *(uint32_t*)(bb + tpos(W + 1) * 4) = *(uint32_t*)&h1;
}

// ---------------- merged prep: LoRA fold + fp16 permute both operands ------
__global__ void prep_kernel(const float* __restrict__ x, const float* __restrict__ w,
                            const float* __restrict__ lA, const float* __restrict__ lB) {
    int tid = threadIdx.x;
    if (blockIdx.x < NDIM) {
        int o = blockIdx.x;
        float bv[16];
#pragma unroll
        for (int r = 0; r < 16; r++) bv[r] = lB[o * 16 + r] * 2.0f;
        const float4* wr = (const float4*)(w + (size_t)o * KDIM);
#pragma unroll 4
        for (int i = 0; i < 4; i++) {
            int j = tid + 256 * i;
            float4 acc = wr[j];
#pragma unroll
            for (int r = 0; r < 16; r++) {
                float4 a = ((const float4*)(lA + (size_t)r * KDIM))[j];
                acc.x += bv[r] * a.x; acc.y += bv[r] * a.y;
                acc.z += bv[r] * a.z; acc.w += bv[r] * a.w;
            }
            cvt_store4(g_wh, o, j * 4, acc);
        }
    } else {
        size_t n4 = (size_t)MDIM * KDIM / 4;
        size_t nblk = (size_t)gridDim.x - NDIM;
        size_t stride = nblk * blockDim.x;
        const float4* in = (const float4*)x;
        for (size_t i = (blockIdx.x - NDIM) * (size_t)blockDim.x + tid; i < n4; i += stride) {
            float4 v = in[i];
            cvt_store4(g_xh, i >> 10, ((int)i & 1023) * 4, v);
        }
    }
}

// --- main GEMM: fp16 m16n8k16, BM=128 BN=256 BK=32, 512 thr, unrolled x3 ---
__global__ __launch_bounds__(NTHR, 1)
void lora_gemm_kernel(const float* __restrict__ bias, float* __restrict__ out) {
    extern __shared__ char smem[];
    const int tid = threadIdx.x;
    const int wid = tid >> 5, lane = tid & 31;
    const int wm = wid >> 2, wn = wid & 3;            // 4 x 4 warps, tile 32x64
    const int m0 = blockIdx.y * BM, n0 = blockIdx.x * BN;
    const uint32_t sbase = smem_u32(smem);

    // per-thread producer pointers (advance +64 B per k-tile)
    const int prow = tid >> 2, pq = tid & 3;
    const char* pA  = (const char*)g_xh + (size_t)(m0 + prow) * (KDIM * 2) + pq * 16;
    const char* pB0 = (const char*)g_wh + (size_t)(n0 + prow) * (KDIM * 2) + pq * 16;
    const char* pB1 = pB0 + (size_t)128 * (KDIM * 2);
    const uint32_t dA = tid * 16;                      // A plane dst
    const uint32_t dB = A_BYTES + tid * 16;            // B plane dst (first half)

#define ISSUE(S)                                                   \
    do {                                                           \
        cp_async16(sbase + (S) * STAGE_BYTES + dA, pA);            \
        cp_async16(sbase + (S) * STAGE_BYTES + dB, pB0);           \
        cp_async16(sbase + (S) * STAGE_BYTES + dB + 8192, pB1);    \
        pA += 64; pB0 += 64; pB1 += 64;                            \
        CP_COMMIT();                                               \
    } while (0)

    float acc[2][8][4];
#pragma unroll
    for (int ma = 0; ma < 2; ma++)
#pragma unroll
        for (int na = 0; na < 8; na++)
#pragma unroll
            for (int j = 0; j < 4; j++) acc[ma][na][j] = 0.0f;

    ISSUE(0);
    ISSUE(1);

    const int g = lane >> 2, t = lane & 3;
    const uint32_t aoff = (wm * 32 + g) * 64 + t * 16;
    const uint32_t boff = A_BYTES + (wn * 64 + g) * 64 + t * 16;

#define STEP(S, PF)                                                            \
    do {                                                                       \
        if (PF) { CP_WAIT1(); } else { CP_WAIT0(); }                           \
        __syncthreads();                                                       \
        if (PF) ISSUE(((S) + 2) % 3);                                          \
        const uint32_t pa = sbase + (S) * STAGE_BYTES + aoff;                  \
        const uint32_t pb = sbase + (S) * STAGE_BYTES + boff;                  \
        uint4 u[2], v[2], w[8];                                                \
        _Pragma("unroll")                                                      \
        for (int ma = 0; ma < 2; ma++) {                                       \
            u[ma] = lds128(pa + ma * (16 * 64));                               \
            v[ma] = lds128(pa + ma * (16 * 64) + 8 * 64);                      \
        }                                                                      \
        _Pragma("unroll")                                                      \
        for (int na = 0; na < 8; na++)                                         \
            w[na] = lds128(pb + na * (8 * 64));                                \
        _Pragma("unroll")                                                      \
        for (int ma = 0; ma < 2; ma++)                                         \
            _Pragma("unroll")                                                  \
            for (int na = 0; na < 8; na++)                                     \
                hmma(acc[ma][na], u[ma].x, v[ma].x, u[ma].y, v[ma].y,          \
                     w[na].x, w[na].y);                                        \
        _Pragma("unroll")                                                      \
        for (int ma = 0; ma < 2; ma++)                                         \
            _Pragma("unroll")                                                  \
            for (int na = 0; na < 8; na++)                                     \
                hmma(acc[ma][na], u[ma].z, v[ma].z, u[ma].w, v[ma].w,          \
                     w[na].z, w[na].w);                                        \
    } while (0)

    // kt 0..125 (42 x 3, stages compile-time), then 126 (s0), 127 (s1)
    for (int i = 0; i < 42; ++i) {
        STEP(0, 1);
        STEP(1, 1);
        STEP(2, 1);
    }
    STEP(0, 0);
    STEP(1, 0);

#undef STEP
#undef ISSUE

    // epilogue: fused bias + coalesced float2 stores
    const int r0 = m0 + wm * 32 + g;
    const int cbase = n0 + wn * 64 + t * 2;
    float2 bv[8];
#pragma unroll
    for (int na = 0; na < 8; na++)
        bv[na] = *(const float2*)(bias + cbase + na * 8);
#pragma unroll
    for (int ma = 0; ma < 2; ma++) {
        size_t row = (size_t)(r0 + ma * 16);
#pragma unroll
        for (int na = 0; na < 8; na++) {
            float2 v0 = make_float2(acc[ma][na][0] + bv[na].x, acc[ma][na][1] + bv[na].y);
            float2 v1 = make_float2(acc[ma][na][2] + bv[na].x, acc[ma][na][3] + bv[na].y);
            *(float2*)(out + row * NDIM + cbase + na * 8) = v0;
            *(float2*)(out + (row + 8) * NDIM + cbase + na * 8) = v1;
        }
    }
}

// ---------------- launch ----------------
extern "C" void kernel_launch(void* const* d_in, const int* in_sizes, int n_in,
                              void* d_out, int out_size) {
    const float* x      = (const float*)d_in[0];
    const float* weight = (const float*)d_in[1];
    const float* bias   = (const float*)d_in[2];
    const float* lora_A = (const float*)d_in[3];
    const float* lora_B = (const float*)d_in[4];
    float* out = (float*)d_out;

    cudaFuncSetAttribute(lora_gemm_kernel, cudaFuncAttributeMaxDynamicSharedMemorySize,
                         SMEM_BYTES);

    prep_kernel<<<NDIM + 8192, 256>>>(x, weight, lora_A, lora_B);
    dim3 grid(NDIM / BN, MDIM / BM);   // n fastest: x panel stays L2-resident
    lora_gemm_kernel<<<grid, NTHR, SMEM_BYTES>>>(bias, out);
}